// round 2
// baseline (speedup 1.0000x reference)
#include <cuda_runtime.h>
#include <math.h>

// Problem dims
#define BB 64
#define TT 512
#define II 256
#define HH 1024
#define OO 10
#define KTOT (HH + II)      // 1280 combined reduction (h part then x part)
#define KT 32               // k-tile
#define NKT (KTOT / KT)     // 40 tiles

#define GRID 128            // 2 b-groups x 64 hj-groups  (all co-resident)
#define NTHREADS 128        // 8 b-threads x 16 hj-threads

// Persistent device state (allowed scratch: __device__ globals)
__device__ float g_h[2][BB * HH];          // double-buffered hidden state
__device__ unsigned int g_count;
__device__ volatile unsigned int g_gen;

__device__ __forceinline__ void grid_sync() {
    __syncthreads();
    if (threadIdx.x == 0) {
        unsigned int my = g_gen;
        __threadfence();
        if (atomicAdd(&g_count, 1u) == GRID - 1) {
            g_count = 0;
            __threadfence();
            g_gen = my + 1;
        } else {
            while (g_gen == my) { }
            __threadfence();
        }
    }
    __syncthreads();
}

// A element: rows are [h | x_t]
__device__ __forceinline__ float loadA(const float* __restrict__ hcur,
                                       const float* __restrict__ x,
                                       int t, int b, int r) {
    return (r < HH) ? hcur[b * HH + r]
                    : x[b * (TT * II) + t * II + (r - HH)];
}

// W element: rows are [Wh ; Wx], column = (gate g, hidden hj)
__device__ __forceinline__ float loadW(const float* __restrict__ Wh,
                                       const float* __restrict__ Wx,
                                       int g, int r, int hj) {
    return (r < HH) ? Wh[(g * HH + r) * HH + hj]
                    : Wx[(g * II + (r - HH)) * HH + hj];
}

__global__ __launch_bounds__(NTHREADS, 1)
void lstm_persistent_kernel(const float* __restrict__ x,
                            const float* __restrict__ Wx,
                            const float* __restrict__ bx,
                            const float* __restrict__ Wh,
                            const float* __restrict__ bh,
                            const float* __restrict__ Wp,
                            const float* __restrict__ bp,
                            float* __restrict__ out)
{
    __shared__ float As[KT * 36];      // [kk][b_local], padded row=36 (16B-aligned float4)
    __shared__ float Bs[KT * 64];      // [kk][g*16 + hj_local]
    __shared__ float red[NTHREADS];
    __shared__ float logits[OO];

    const int tid = threadIdx.x;
    const int bgrp  = blockIdx.x & 1;      // 0..1  -> 32 batch rows
    const int hjgrp = blockIdx.x >> 1;     // 0..63 -> 16 hidden cols
    const int b0  = bgrp * 32;
    const int hj0 = hjgrp * 16;

    const int thj = tid & 15;              // 0..15 hidden col within tile
    const int tb  = tid >> 4;              // 0..7  -> 4 batch rows each
    const int hj  = hj0 + thj;

    // load-phase thread mappings (coalesced along k / along columns)
    const int a_kk = tid & 31;             // A: kk contiguous within warp
    const int a_b  = tid >> 5;             // 0..3, each covers 8 local b rows
    const int b_c  = tid & 63;             // B: column contiguous within warp
    const int b_k  = tid >> 6;             // 0..1

    // zero initial hidden state (buffer 0)
    for (int idx = blockIdx.x * NTHREADS + tid; idx < BB * HH; idx += GRID * NTHREADS)
        g_h[0][idx] = 0.0f;

    // per-thread gate biases (bx + bh folded once)
    float bias[4];
#pragma unroll
    for (int g = 0; g < 4; g++)
        bias[g] = bh[g * HH + hj] + bx[g * HH + hj];

    // cell state lives in registers for the whole sequence
    float c[4] = {0.f, 0.f, 0.f, 0.f};

    grid_sync();   // h0 visible everywhere

    for (int t = 0; t < TT; t++) {
        const float* hcur = g_h[t & 1];
        float*       hnxt = g_h[(t + 1) & 1];

        float acc[4][4];
#pragma unroll
        for (int g = 0; g < 4; g++)
#pragma unroll
            for (int q = 0; q < 4; q++) acc[g][q] = 0.f;

        // register prefetch of tile 0
        float pa[8], pb[16];
#pragma unroll
        for (int q = 0; q < 8; q++)
            pa[q] = loadA(hcur, x, t, b0 + a_b * 8 + q, a_kk);
#pragma unroll
        for (int q = 0; q < 16; q++)
            pb[q] = loadW(Wh, Wx, b_c >> 4, b_k + q * 2, hj0 + (b_c & 15));

        for (int kt = 0; kt < NKT; kt++) {
            // stage prefetched tile into smem
#pragma unroll
            for (int q = 0; q < 8; q++)
                As[a_kk * 36 + a_b * 8 + q] = pa[q];
#pragma unroll
            for (int q = 0; q < 16; q++)
                Bs[(b_k + q * 2) * 64 + b_c] = pb[q];
            __syncthreads();

            // prefetch next tile (global loads overlap with FMA below)
            if (kt + 1 < NKT) {
                const int k0 = (kt + 1) * KT;
#pragma unroll
                for (int q = 0; q < 8; q++)
                    pa[q] = loadA(hcur, x, t, b0 + a_b * 8 + q, k0 + a_kk);
#pragma unroll
                for (int q = 0; q < 16; q++)
                    pb[q] = loadW(Wh, Wx, b_c >> 4, k0 + b_k + q * 2, hj0 + (b_c & 15));
            }

            // 32-deep rank-1 updates: 16 FFMA + 5 LDS per k per thread
#pragma unroll
            for (int kk = 0; kk < KT; kk++) {
                float4 av = *(const float4*)&As[kk * 36 + tb * 4];
                float w0 = Bs[kk * 64 +  0 + thj];
                float w1 = Bs[kk * 64 + 16 + thj];
                float w2 = Bs[kk * 64 + 32 + thj];
                float w3 = Bs[kk * 64 + 48 + thj];
                acc[0][0] += av.x * w0; acc[0][1] += av.y * w0;
                acc[0][2] += av.z * w0; acc[0][3] += av.w * w0;
                acc[1][0] += av.x * w1; acc[1][1] += av.y * w1;
                acc[1][2] += av.z * w1; acc[1][3] += av.w * w1;
                acc[2][0] += av.x * w2; acc[2][1] += av.y * w2;
                acc[2][2] += av.z * w2; acc[2][3] += av.w * w2;
                acc[3][0] += av.x * w3; acc[3][1] += av.y * w3;
                acc[3][2] += av.z * w3; acc[3][3] += av.w * w3;
            }
            __syncthreads();
        }

        // gate epilogue: thread owns all 4 gates of its 4 (b, hj) cells
#pragma unroll
        for (int q = 0; q < 4; q++) {
            float zg = acc[0][q] + bias[0];
            float zi = acc[1][q] + bias[1];
            float zf = acc[2][q] + bias[2];
            float zo = acc[3][q] + bias[3];
            float gg = tanhf(zg);
            float ii = 1.0f / (1.0f + __expf(-zi));
            float ff = 1.0f / (1.0f + __expf(-zf));
            float oo = 1.0f / (1.0f + __expf(-zo));
            c[q] = gg * ii + c[q] * ff;
            hnxt[(b0 + tb * 4 + q) * HH + hj] = tanhf(c[q]) * oo;
        }

        grid_sync();   // new h visible before next step's GEMM
    }

    // final projection + softmax: CTA b handles batch row b (final h is in buffer 0)
    if (blockIdx.x < BB) {
        const int b = blockIdx.x;
        const float* hfin = g_h[0] + b * HH;
        float part[OO];
#pragma unroll
        for (int o = 0; o < OO; o++) part[o] = 0.f;
        for (int k = tid; k < HH; k += NTHREADS) {
            float hv = hfin[k];
#pragma unroll
            for (int o = 0; o < OO; o++)
                part[o] += hv * Wp[k * OO + o];
        }
        for (int o = 0; o < OO; o++) {
            red[tid] = part[o];
            __syncthreads();
            for (int s = NTHREADS / 2; s > 0; s >>= 1) {
                if (tid < s) red[tid] += red[tid + s];
                __syncthreads();
            }
            if (tid == 0) logits[o] = red[0] + bp[o];
            __syncthreads();
        }
        if (tid == 0) {
            float m = logits[0];
#pragma unroll
            for (int o = 1; o < OO; o++) m = fmaxf(m, logits[o]);
            float s = 0.f, e[OO];
#pragma unroll
            for (int o = 0; o < OO; o++) { e[o] = expf(logits[o] - m); s += e[o]; }
            float inv = 1.0f / s;
#pragma unroll
            for (int o = 0; o < OO; o++) out[b * OO + o] = e[o] * inv;
        }
    }
}

extern "C" void kernel_launch(void* const* d_in, const int* in_sizes, int n_in,
                              void* d_out, int out_size) {
    const float* x  = (const float*)d_in[0];
    const float* Wx = (const float*)d_in[1];
    const float* bx = (const float*)d_in[2];
    const float* Wh = (const float*)d_in[3];
    const float* bh = (const float*)d_in[4];
    const float* Wp = (const float*)d_in[5];
    const float* bp = (const float*)d_in[6];
    float* out = (float*)d_out;

    lstm_persistent_kernel<<<GRID, NTHREADS>>>(x, Wx, bx, Wh, bh, Wp, bp, out);
}